// round 12
// baseline (speedup 1.0000x reference)
#include <cuda_runtime.h>
#include <cuda_bf16.h>
#include <cuda_fp16.h>
#include <math.h>
#include <cstdint>

#define CB   2
#define CT   2048
#define CDIM 1024
#define CH   16
#define CDH  64
#define MROWS (CB*CT)       // 4096
#define KSPLIT (3*CDIM)     // 3072
#define NSTAGE (KSPLIT/64)  // 48

// ---------------- scratch (device globals) ----------------------------------
__device__ float g_qkv[MROWS*3*CDIM];          // fused QKV projection output
__device__ __nv_bfloat16 g_a [MROWS*KSPLIT];   // split activations [Ah|Ah|Al]
__device__ __nv_bfloat16 g_w3[3*CDIM*KSPLIT];  // Wq|Wk|Wv split [Bh|Bl|Bh]
__device__ __nv_bfloat16 g_wo[CDIM*KSPLIT];
// pre-split attention operands (fp16)
__device__ __half g_qh[MROWS*CDIM];
__device__ __half g_ql[MROWS*CDIM];
__device__ __half g_kh[MROWS*CDIM];
__device__ __half g_vh[MROWS*CDIM];

__device__ __forceinline__ uint32_t smem_u32(const void* p) {
    uint32_t a;
    asm("{ .reg .u64 t; cvta.to.shared.u64 t, %1; cvt.u32.u64 %0, t; }"
        : "=r"(a) : "l"(p));
    return a;
}
__device__ __forceinline__ void ldsm4(uint32_t* r, uint32_t addr) {
    asm volatile("ldmatrix.sync.aligned.m8n8.x4.shared.b16 {%0,%1,%2,%3}, [%4];"
        : "=r"(r[0]), "=r"(r[1]), "=r"(r[2]), "=r"(r[3]) : "r"(addr));
}
__device__ __forceinline__ void ldsm2t(uint32_t* r, uint32_t addr) {
    asm volatile("ldmatrix.sync.aligned.m8n8.x2.trans.shared.b16 {%0,%1}, [%2];"
        : "=r"(r[0]), "=r"(r[1]) : "r"(addr));
}
__device__ __forceinline__ void mma16816(float* d, const uint32_t* a, const uint32_t* b) {
    asm volatile("mma.sync.aligned.m16n8k16.row.col.f32.bf16.bf16.f32 "
        "{%0,%1,%2,%3}, {%4,%5,%6,%7}, {%8,%9}, {%0,%1,%2,%3};"
        : "+f"(d[0]), "+f"(d[1]), "+f"(d[2]), "+f"(d[3])
        : "r"(a[0]), "r"(a[1]), "r"(a[2]), "r"(a[3]), "r"(b[0]), "r"(b[1]));
}
__device__ __forceinline__ void mma16816h(float* d, const uint32_t* a, const uint32_t* b) {
    asm volatile("mma.sync.aligned.m16n8k16.row.col.f32.f16.f16.f32 "
        "{%0,%1,%2,%3}, {%4,%5,%6,%7}, {%8,%9}, {%0,%1,%2,%3};"
        : "+f"(d[0]), "+f"(d[1]), "+f"(d[2]), "+f"(d[3])
        : "r"(a[0]), "r"(a[1]), "r"(a[2]), "r"(a[3]), "r"(b[0]), "r"(b[1]));
}
__device__ __forceinline__ float ex2f(float x) {
    float y; asm("ex2.approx.f32 %0, %1;" : "=f"(y) : "f"(x)); return y;
}
__device__ __forceinline__ uint32_t packbf(float a, float b) {
    __nv_bfloat162 t = __floats2bfloat162_rn(a, b);
    return *(uint32_t*)&t;
}
__device__ __forceinline__ uint32_t packhf(float a, float b) {
    __half2 t = __floats2half2_rn(a, b);
    return *(uint32_t*)&t;
}
#define CPA16(dst, src) \
    asm volatile("cp.async.cg.shared.global [%0], [%1], 16;" :: "r"(dst), "l"(src))

// ---------------------------------------------------------------------------
// split activations: fp32 [rows x 1024] -> bf16 [rows x 3072] [h|h|l]
// ---------------------------------------------------------------------------
__global__ void split_kernel(const float* __restrict__ in,
                             __nv_bfloat16* __restrict__ out, int rows)
{
    int i = blockIdx.x * blockDim.x + threadIdx.x;
    if (i >= rows * 256) return;
    int r  = i >> 8;
    int c4 = (i & 255) * 4;
    float4 v = *(const float4*)(in + (size_t)r * CDIM + c4);
    __nv_bfloat16 h[4], l[4];
    float vs[4] = {v.x, v.y, v.z, v.w};
#pragma unroll
    for (int t = 0; t < 4; t++) {
        h[t] = __float2bfloat16(vs[t]);
        l[t] = __float2bfloat16(vs[t] - __bfloat162float(h[t]));
    }
    __nv_bfloat16* o = out + (size_t)r * KSPLIT + c4;
    *(ushort4*)(o)            = *(ushort4*)h;
    *(ushort4*)(o + CDIM)     = *(ushort4*)h;
    *(ushort4*)(o + 2 * CDIM) = *(ushort4*)l;
}

// 4 weight splits in one launch: [h|l|h]. z<3 -> g_w3 block z, z==3 -> g_wo.
__global__ void splitw_kernel(const float* __restrict__ Wq, const float* __restrict__ Wk,
                              const float* __restrict__ Wv, const float* __restrict__ Wo)
{
    int z = blockIdx.y;
    const float* in = (z == 0) ? Wq : (z == 1) ? Wk : (z == 2) ? Wv : Wo;
    __nv_bfloat16* out = (z < 3) ? (g_w3 + (size_t)z * CDIM * KSPLIT) : g_wo;
    int i = blockIdx.x * blockDim.x + threadIdx.x;
    if (i >= CDIM * 256) return;
    int r  = i >> 8;
    int c4 = (i & 255) * 4;
    float4 v = *(const float4*)(in + (size_t)r * CDIM + c4);
    __nv_bfloat16 h[4], l[4];
    float vs[4] = {v.x, v.y, v.z, v.w};
#pragma unroll
    for (int t = 0; t < 4; t++) {
        h[t] = __float2bfloat16(vs[t]);
        l[t] = __float2bfloat16(vs[t] - __bfloat162float(h[t]));
    }
    __nv_bfloat16* o = out + (size_t)r * KSPLIT + c4;
    *(ushort4*)(o)            = *(ushort4*)h;
    *(ushort4*)(o + CDIM)     = *(ushort4*)l;
    *(ushort4*)(o + 2 * CDIM) = *(ushort4*)h;
}

// ---------------------------------------------------------------------------
// mma.sync bf16 NT GEMM: C = A'[M,3072] * B'[N,3072]^T, fp32 accum.
// CTA 128x128, 8 warps 2(m)x4(n) (64x32 warp tiles), 3-stage cp.async,
// 96KB smem -> 2 CTAs/SM.
// ---------------------------------------------------------------------------
#define GEMM_SMEM (3*32768)

__global__ __launch_bounds__(256, 2)
void gemm_mma_kernel(const __nv_bfloat16* __restrict__ A,
                     const __nv_bfloat16* __restrict__ B,
                     float* __restrict__ C, int M, int N)
{
    extern __shared__ char sm[];
    const uint32_t smb = smem_u32(sm);
    const int tid  = threadIdx.x;
    const int lane = tid & 31;
    const int wid  = tid >> 5;
    const int wm = wid & 1;
    const int wn = wid >> 1;
    const int bm = blockIdx.y * 128;
    const int bn = blockIdx.x * 128;

    const __nv_bfloat16* Ag = A + (size_t)bm * KSPLIT;
    const __nv_bfloat16* Bg = B + (size_t)bn * KSPLIT;

    auto prefetch = [&](int s) {
        const int buf = s % 3;
        const uint32_t ab = smb + buf * 32768;
        const uint32_t bb = ab + 16384;
        const __nv_bfloat16* a = Ag + s * 64;
        const __nv_bfloat16* b = Bg + s * 64;
#pragma unroll
        for (int i = 0; i < 4; i++) {
            int idx = tid + i * 256;
            int r = idx >> 3, ch = idx & 7;
            uint32_t o = r * 128 + ch * 16; o ^= (o >> 3) & 0x70;
            CPA16(ab + o, a + (size_t)r * KSPLIT + ch * 8);
            CPA16(bb + o, b + (size_t)r * KSPLIT + ch * 8);
        }
        asm volatile("cp.async.commit_group;");
    };

    float acc[4][4][4];
#pragma unroll
    for (int mt = 0; mt < 4; mt++)
#pragma unroll
        for (int nt = 0; nt < 4; nt++)
#pragma unroll
            for (int e = 0; e < 4; e++) acc[mt][nt][e] = 0.f;

    prefetch(0); prefetch(1); prefetch(2);

    for (int s = 0; s < NSTAGE; s++) {
        asm volatile("cp.async.wait_group 2;");
        __syncthreads();
        const int buf = s % 3;
        const uint32_t ab = smb + buf * 32768;
        const uint32_t bb = ab + 16384;
#pragma unroll
        for (int kk = 0; kk < 4; kk++) {
            uint32_t af[4][4];
            const int ar = wm * 64 + (lane & 15);
            const int ac = kk * 2 + (lane >> 4);
#pragma unroll
            for (int mt = 0; mt < 4; mt++) {
                uint32_t o = (ar + mt * 16) * 128 + ac * 16; o ^= (o >> 3) & 0x70;
                ldsm4(af[mt], ab + o);
            }
            uint32_t bfr[4][2];
            const int br = wn * 32 + ((lane >> 4) << 3) + (lane & 7);
            const int bc = kk * 2 + ((lane >> 3) & 1);
#pragma unroll
            for (int np = 0; np < 2; np++) {
                uint32_t o = (br + np * 16) * 128 + bc * 16; o ^= (o >> 3) & 0x70;
                uint32_t t4[4];
                ldsm4(t4, bb + o);
                bfr[np*2][0] = t4[0]; bfr[np*2][1] = t4[1];
                bfr[np*2+1][0] = t4[2]; bfr[np*2+1][1] = t4[3];
            }
#pragma unroll
            for (int mt = 0; mt < 4; mt++)
#pragma unroll
                for (int nt = 0; nt < 4; nt++)
                    mma16816(acc[mt][nt], af[mt], bfr[nt]);
        }
        __syncthreads();
        if (s + 3 < NSTAGE) prefetch(s + 3);
        else asm volatile("cp.async.commit_group;");
    }

    const int er = lane >> 2;
    const int ec = (lane & 3) * 2;
#pragma unroll
    for (int mt = 0; mt < 4; mt++) {
        int r0 = bm + wm * 64 + mt * 16 + er;
#pragma unroll
        for (int nt = 0; nt < 4; nt++) {
            int cc = bn + wn * 32 + nt * 8 + ec;
            *(float2*)(C + (size_t)r0 * N + cc) = make_float2(acc[mt][nt][0], acc[mt][nt][1]);
            *(float2*)(C + (size_t)(r0 + 8) * N + cc) = make_float2(acc[mt][nt][2], acc[mt][nt][3]);
        }
    }
}

// ---------------------------------------------------------------------------
// fused RoPE + convert. Reads fused qkv [rows x 3072].
// q -> fp16 2-term (pre-scaled by 0.125*log2e), k -> fp16, v -> fp16.
// ---------------------------------------------------------------------------
#define QSCALE 0.180336878f   // 0.125 * log2(e)

__global__ void ropeconv_kernel(const float* __restrict__ qkv)
{
    int i = blockIdx.x * blockDim.x + threadIdx.x;
    if (i >= MROWS * CH * 4) return;
    const int c8   = (i & 3) * 8;
    const int rest = i >> 2;                 // (b*CT+t)*CH + h
    const int row  = rest >> 4;              // b*CT + t
    const int hh   = rest & 15;
    const int t    = row & (CT - 1);
    const size_t base  = (size_t)rest * CDH;             // output layout
    const size_t qbase = (size_t)row * 3072 + hh * CDH;  // fused input
    const size_t kbase = qbase + CDIM;
    const size_t vbase = qbase + 2 * CDIM;

    float q0[8], q1[8], k0[8], k1[8], v0[8], v1[8];
    *(float4*)(q0)   = *(const float4*)(qkv + qbase + c8);
    *(float4*)(q0+4) = *(const float4*)(qkv + qbase + c8 + 4);
    *(float4*)(q1)   = *(const float4*)(qkv + qbase + c8 + 32);
    *(float4*)(q1+4) = *(const float4*)(qkv + qbase + c8 + 36);
    *(float4*)(k0)   = *(const float4*)(qkv + kbase + c8);
    *(float4*)(k0+4) = *(const float4*)(qkv + kbase + c8 + 4);
    *(float4*)(k1)   = *(const float4*)(qkv + kbase + c8 + 32);
    *(float4*)(k1+4) = *(const float4*)(qkv + kbase + c8 + 36);
    *(float4*)(v0)   = *(const float4*)(qkv + vbase + c8);
    *(float4*)(v0+4) = *(const float4*)(qkv + vbase + c8 + 4);
    *(float4*)(v1)   = *(const float4*)(qkv + vbase + c8 + 32);
    *(float4*)(v1+4) = *(const float4*)(qkv + vbase + c8 + 36);

#pragma unroll
    for (int d = 0; d < 8; d++) {
        float invf = expf(-(float)(c8 + d) * (1.0f/32.0f) * logf(10000.0f));
        float ang = (float)t * invf, sv, cv;
        sincosf(ang, &sv, &cv);
        float a = q0[d], bq = q1[d];
        q0[d] = a * cv - bq * sv;  q1[d] = bq * cv + a * sv;
        float c = k0[d], dk = k1[d];
        k0[d] = c * cv - dk * sv;  k1[d] = dk * cv + c * sv;
    }

    uint32_t hw[4], lw[4];
    auto emitq = [&](const float* src, __half* oh, __half* ol) {
#pragma unroll
        for (int e = 0; e < 4; e++) {
            float a = src[2*e] * QSCALE, b = src[2*e+1] * QSCALE;
            float ah = __half2float(__float2half_rn(a));
            float bh = __half2float(__float2half_rn(b));
            hw[e] = packhf(a, b);
            lw[e] = packhf(a - ah, b - bh);
        }
        *(uint4*)oh = *(uint4*)hw;
        *(uint4*)ol = *(uint4*)lw;
    };
    auto emith = [&](const float* src, __half* oh) {
#pragma unroll
        for (int e = 0; e < 4; e++)
            hw[e] = packhf(src[2*e], src[2*e+1]);
        *(uint4*)oh = *(uint4*)hw;
    };
    emitq(q0, g_qh + base + c8,      g_ql + base + c8);
    emitq(q1, g_qh + base + c8 + 32, g_ql + base + c8 + 32);
    emith(k0, g_kh + base + c8);
    emith(k1, g_kh + base + c8 + 32);
    emith(v0, g_vh + base + c8);
    emith(v1, g_vh + base + c8 + 32);
}

// ---------------------------------------------------------------------------
// Tensor-core causal flash attention.
// CTA = (b, h, 128 q-rows). 8 warps 2(M)x4(N). j-tiles of 128.
// S: fp16 (qh+ql).kh, 8 k-steps. PV: fp16 P x fp16 V, 8 k-steps.
// K/V double-buffered. Epilogue writes split [h|h|l] bf16 into g_a.
// ---------------------------------------------------------------------------
#define AQH 0
#define AQL 16384
#define AKV 32768          // + buf*32768 : KH +0, VH +16384
#define APH 98304
#define ARED 133120
#define ATT_SMEM 137216
#define PROW 272           // P row stride bytes

__global__ __launch_bounds__(256, 1)
void attn_tc_kernel()
{
    extern __shared__ char sm[];
    const uint32_t smb = smem_u32(sm);
    float* red0 = (float*)(sm + ARED);
    float* red1 = (float*)(sm + ARED + 2048);

    const int tid  = threadIdx.x;
    const int lane = tid & 31;
    const int wid  = tid >> 5;
    const int wm = wid & 1, wn = wid >> 1;
    const int qt = gridDim.x - 1 - blockIdx.x;
    const int h  = blockIdx.y, b = blockIdx.z;
    const int q0 = qt * 128;

    // Q tiles (qh + ql)
#pragma unroll
    for (int it = 0; it < 4; it++) {
        int idx = tid + it * 256;
        int r = idx >> 3, ch = idx & 7;
        uint32_t o = r * 128 + ch * 16; o ^= (o >> 3) & 0x70;
        size_t so = ((size_t)(b*CT + q0 + r)) * CDIM + h * CDH + ch * 8;
        CPA16(smb + AQH + o, g_qh + so);
        CPA16(smb + AQL + o, g_ql + so);
    }
    asm volatile("cp.async.commit_group;");

    auto pf_kv = [&](int jtn) {
        const uint32_t kvb = smb + AKV + (jtn & 1) * 32768;
        const int j0n = jtn * 128;
#pragma unroll
        for (int it = 0; it < 4; it++) {
            int idx = tid + it * 256;
            int r = idx >> 3, ch = idx & 7;
            uint32_t o = r * 128 + ch * 16; o ^= (o >> 3) & 0x70;
            size_t so = ((size_t)(b*CT + j0n + r)) * CDIM + h * CDH + ch * 8;
            CPA16(kvb + o,         g_kh + so);
            CPA16(kvb + 16384 + o, g_vh + so);
        }
    };
    pf_kv(0);
    asm volatile("cp.async.commit_group;");

    float m_run[4][2], l_run[4][2];
    float oacc[4][2][4];
#pragma unroll
    for (int mt = 0; mt < 4; mt++)
#pragma unroll
        for (int p = 0; p < 2; p++) {
            m_run[mt][p] = -1e30f; l_run[mt][p] = 0.f;
            oacc[mt][p][0]=oacc[mt][p][1]=oacc[mt][p][2]=oacc[mt][p][3]=0.f;
        }

    const int rbase = (lane >> 2);
    const int cbase = (lane & 3) * 2;

    for (int jt = 0; jt <= qt; jt++) {
        __syncthreads();
        if (jt < qt) pf_kv(jt + 1);
        asm volatile("cp.async.commit_group;");
        asm volatile("cp.async.wait_group 1;");
        __syncthreads();

        const uint32_t kvb = smb + AKV + (jt & 1) * 32768;

        // ---- S = (qh + ql) . kh^T   (8 fp16 k16 steps) ----
        float sacc[4][4][4];
#pragma unroll
        for (int mt = 0; mt < 4; mt++)
#pragma unroll
            for (int nt = 0; nt < 4; nt++)
#pragma unroll
                for (int e = 0; e < 4; e++) sacc[mt][nt][e] = 0.f;

#pragma unroll
        for (int kk = 0; kk < 8; kk++) {
            const uint32_t qb = smb + (kk < 4 ? AQH : AQL);
            const int kin = kk & 3;
            uint32_t af[4][4];
            const int ar = wm * 64 + (lane & 15);
            const int ac = kin * 2 + (lane >> 4);
#pragma unroll
            for (int mt = 0; mt < 4; mt++) {
                uint32_t o = (ar + mt * 16) * 128 + ac * 16; o ^= (o >> 3) & 0x70;
                ldsm4(af[mt], qb + o);
            }
            uint32_t bfr[4][2];
            const int br = wn * 32 + ((lane >> 4) << 3) + (lane & 7);
            const int bc = kin * 2 + ((lane >> 3) & 1);
#pragma unroll
            for (int np = 0; np < 2; np++) {
                uint32_t o = (br + np * 16) * 128 + bc * 16; o ^= (o >> 3) & 0x70;
                uint32_t t4[4];
                ldsm4(t4, kvb + o);
                bfr[np*2][0] = t4[0]; bfr[np*2][1] = t4[1];
                bfr[np*2+1][0] = t4[2]; bfr[np*2+1][1] = t4[3];
            }
#pragma unroll
            for (int mt = 0; mt < 4; mt++)
#pragma unroll
                for (int nt = 0; nt < 4; nt++)
                    mma16816h(sacc[mt][nt], af[mt], bfr[nt]);
        }

        if (jt == qt) {
#pragma unroll
            for (int mt = 0; mt < 4; mt++)
#pragma unroll
                for (int nt = 0; nt < 4; nt++)
#pragma unroll
                    for (int e = 0; e < 4; e++) {
                        int row = wm*64 + mt*16 + rbase + (e >> 1) * 8;
                        int col = wn*32 + nt*8 + cbase + (e & 1);
                        if (col > row) sacc[mt][nt][e] = -1e30f;
                    }
        }

        // ---- row max ----
        float mnew[4][2], alpha[4][2];
#pragma unroll
        for (int mt = 0; mt < 4; mt++)
#pragma unroll
            for (int p = 0; p < 2; p++) {
                float v = fmaxf(fmaxf(sacc[mt][0][2*p], sacc[mt][0][2*p+1]),
                                fmaxf(sacc[mt][1][2*p], sacc[mt][1][2*p+1]));
                v = fmaxf(v, fmaxf(fmaxf(sacc[mt][2][2*p], sacc[mt][2][2*p+1]),
                                   fmaxf(sacc[mt][3][2*p], sacc[mt][3][2*p+1])));
                v = fmaxf(v, __shfl_xor_sync(0xffffffffu, v, 1));
                v = fmaxf(v, __shfl_xor_sync(0xffffffffu, v, 2));
                if ((lane & 3) == 0)
                    red0[wn * 128 + wm*64 + mt*16 + rbase + p*8] = v;
            }
        __syncthreads();
#pragma unroll
        for (int mt = 0; mt < 4; mt++)
#pragma unroll
            for (int p = 0; p < 2; p++) {
                int row = wm*64 + mt*16 + rbase + p*8;
                float v = fmaxf(fmaxf(red0[row], red0[128 + row]),
                                fmaxf(red0[256 + row], red0[384 + row]));
                float mn = fmaxf(m_run[mt][p], v);
                alpha[mt][p] = ex2f(m_run[mt][p] - mn);
                mnew[mt][p] = mn;
                m_run[mt][p] = mn;
            }

        // ---- P = exp2(S - m) -> fp16 smem; row sums; rescale O ----
        float lsum[4][2] = {{0.f,0.f},{0.f,0.f},{0.f,0.f},{0.f,0.f}};
#pragma unroll
        for (int mt = 0; mt < 4; mt++) {
#pragma unroll
            for (int nt = 0; nt < 4; nt++) {
                int col = wn*32 + nt*8 + cbase;
#pragma unroll
                for (int p = 0; p < 2; p++) {
                    int row = wm*64 + mt*16 + rbase + p*8;
                    float p0 = ex2f(sacc[mt][nt][2*p]   - mnew[mt][p]);
                    float p1 = ex2f(sacc[mt][nt][2*p+1] - mnew[mt][p]);
                    lsum[mt][p] += p0 + p1;
                    *(uint32_t*)(sm + APH + row*PROW + col*2) = packhf(p0, p1);
                }
            }
        }
#pragma unroll
        for (int mt = 0; mt < 4; mt++)
#pragma unroll
            for (int p = 0; p < 2; p++) {
                float v = lsum[mt][p];
                v += __shfl_xor_sync(0xffffffffu, v, 1);
                v += __shfl_xor_sync(0xffffffffu, v, 2);
                if ((lane & 3) == 0)
                    red1[wn * 128 + wm*64 + mt*16 + rbase + p*8] = v;
                oacc[mt][0][2*p]   *= alpha[mt][p];
                oacc[mt][0][2*p+1] *= alpha[mt][p];
                oacc[mt][1][2*p]   *= alpha[mt][p];
                oacc[mt][1][2*p+1] *= alpha[mt][p];
            }
        __syncthreads();
#pragma unroll
        for (int mt = 0; mt < 4; mt++)
#pragma unroll
            for (int p = 0; p < 2; p++) {
                int row = wm*64 + mt*16 + rbase + p*8;
                float v = red1[row] + red1[128 + row] + red1[256 + row] + red1[384 + row];
                l_run[mt][p] = l_run[mt][p] * alpha[mt][p] + v;
            }

        // ---- PV: fp16 P x fp16 V ----
        const uint32_t vb = kvb + 16384;
#pragma unroll
        for (int kk = 0; kk < 8; kk++) {
            uint32_t af[4][4];
            const int ar = wm * 64 + (lane & 15);
            const int ac = kk * 2 + (lane >> 4);
#pragma unroll
            for (int mt = 0; mt < 4; mt++)
                ldsm4(af[mt], smb + APH + (ar + mt*16)*PROW + ac*16);
            uint32_t bv[2][2];
            const int vr = kk * 16 + (lane & 15);
#pragma unroll
            for (int np = 0; np < 2; np++) {
                uint32_t o = vr * 128 + (wn*16 + np*8) * 2; o ^= (o >> 3) & 0x70;
                ldsm2t(bv[np], vb + o);
            }
#pragma unroll
            for (int mt = 0; mt < 4; mt++)
#pragma unroll
                for (int np = 0; np < 2; np++)
                    mma16816h(oacc[mt][np], af[mt], bv[np]);
        }
    }

    // ---- epilogue: write split activations [h|h|l] straight into g_a ----
#pragma unroll
    for (int mt = 0; mt < 4; mt++)
#pragma unroll
        for (int p = 0; p < 2; p++) {
            float inv = 1.0f / l_run[mt][p];
            size_t rg = (size_t)(b*CT) + q0 + wm*64 + mt*16 + rbase + p*8;
#pragma unroll
            for (int np = 0; np < 2; np++) {
                int col = h * CDH + wn*16 + np*8 + cbase;
                float v0 = oacc[mt][np][2*p] * inv;
                float v1 = oacc[mt][np][2*p+1] * inv;
                float h0 = __bfloat162float(__float2bfloat16_rn(v0));
                float h1 = __bfloat162float(__float2bfloat16_rn(v1));
                uint32_t hwv = packbf(v0, v1);
                uint32_t lwv = packbf(v0 - h0, v1 - h1);
                __nv_bfloat16* oa = g_a + rg * KSPLIT + col;
                *(uint32_t*)(oa)            = hwv;
                *(uint32_t*)(oa + CDIM)     = hwv;
                *(uint32_t*)(oa + 2*CDIM)   = lwv;
            }
        }
}

// ---------------------------------------------------------------------------
extern "C" void kernel_launch(void* const* d_in, const int* in_sizes, int n_in,
                              void* d_out, int out_size)
{
    const float* x  = (const float*)d_in[0];
    const float* Wq = (const float*)d_in[1];
    const float* Wk = (const float*)d_in[2];
    const float* Wv = (const float*)d_in[3];
    const float* Wo = (const float*)d_in[4];
    float* out = (float*)d_out;

    float *qkvp;
    __nv_bfloat16 *a2, *w3, *wo2;
    cudaGetSymbolAddress((void**)&qkvp, g_qkv);
    cudaGetSymbolAddress((void**)&a2,  g_a);
    cudaGetSymbolAddress((void**)&w3,  g_w3);
    cudaGetSymbolAddress((void**)&wo2, g_wo);

    cudaFuncSetAttribute(gemm_mma_kernel,
                         cudaFuncAttributeMaxDynamicSharedMemorySize, GEMM_SMEM);
    cudaFuncSetAttribute(attn_tc_kernel,
                         cudaFuncAttributeMaxDynamicSharedMemorySize, ATT_SMEM);

    int na = MROWS * 256;
    split_kernel<<<(na + 255)/256, 256>>>(x, a2, MROWS);
    splitw_kernel<<<dim3(CDIM, 4), 256>>>(Wq, Wk, Wv, Wo);

    // fused QKV projection: C[4096, 3072], grid 24x32 = 768 CTAs
    gemm_mma_kernel<<<dim3(3*CDIM/128, MROWS/128), 256, GEMM_SMEM>>>(
        a2, w3, qkvp, MROWS, 3*CDIM);

    ropeconv_kernel<<<(MROWS*CH*4 + 255)/256, 256>>>(qkvp);

    attn_tc_kernel<<<dim3(CT/128, CH, CB), 256, ATT_SMEM>>>();

    gemm_mma_kernel<<<dim3(CDIM/128, MROWS/128), 256, GEMM_SMEM>>>(
        a2, wo2, out, MROWS, CDIM);
}

// round 14
// speedup vs baseline: 1.4550x; 1.4550x over previous
#include <cuda_runtime.h>
#include <cuda_bf16.h>
#include <cuda_fp16.h>
#include <math.h>
#include <cstdint>

#define CB   2
#define CT   2048
#define CDIM 1024
#define CH   16
#define CDH  64
#define MROWS (CB*CT)       // 4096
#define KSPLIT (3*CDIM)     // 3072
#define NSTAGE (KSPLIT/64)  // 48

// ---------------- scratch (device globals) ----------------------------------
__device__ float g_qkv[MROWS*3*CDIM];          // fused QKV projection output
__device__ __nv_bfloat16 g_a [MROWS*KSPLIT];   // split activations [Ah|Ah|Al]
__device__ __nv_bfloat16 g_w3[3*CDIM*KSPLIT];  // Wq|Wk|Wv split [Bh|Bl|Bh]
__device__ __nv_bfloat16 g_wo[CDIM*KSPLIT];
// pre-split attention operands (R11 layout: bf16 q/k h+l, fp16 v)
__device__ __nv_bfloat16 g_qh[MROWS*CDIM];
__device__ __nv_bfloat16 g_ql[MROWS*CDIM];
__device__ __nv_bfloat16 g_kh[MROWS*CDIM];
__device__ __nv_bfloat16 g_kl[MROWS*CDIM];
__device__ __half        g_vh[MROWS*CDIM];

__device__ __forceinline__ uint32_t smem_u32(const void* p) {
    uint32_t a;
    asm("{ .reg .u64 t; cvta.to.shared.u64 t, %1; cvt.u32.u64 %0, t; }"
        : "=r"(a) : "l"(p));
    return a;
}
__device__ __forceinline__ void ldsm4(uint32_t* r, uint32_t addr) {
    asm volatile("ldmatrix.sync.aligned.m8n8.x4.shared.b16 {%0,%1,%2,%3}, [%4];"
        : "=r"(r[0]), "=r"(r[1]), "=r"(r[2]), "=r"(r[3]) : "r"(addr));
}
__device__ __forceinline__ void ldsm2t(uint32_t* r, uint32_t addr) {
    asm volatile("ldmatrix.sync.aligned.m8n8.x2.trans.shared.b16 {%0,%1}, [%2];"
        : "=r"(r[0]), "=r"(r[1]) : "r"(addr));
}
__device__ __forceinline__ void mma16816(float* d, const uint32_t* a, const uint32_t* b) {
    asm volatile("mma.sync.aligned.m16n8k16.row.col.f32.bf16.bf16.f32 "
        "{%0,%1,%2,%3}, {%4,%5,%6,%7}, {%8,%9}, {%0,%1,%2,%3};"
        : "+f"(d[0]), "+f"(d[1]), "+f"(d[2]), "+f"(d[3])
        : "r"(a[0]), "r"(a[1]), "r"(a[2]), "r"(a[3]), "r"(b[0]), "r"(b[1]));
}
__device__ __forceinline__ void mma16816h(float* d, const uint32_t* a, const uint32_t* b) {
    asm volatile("mma.sync.aligned.m16n8k16.row.col.f32.f16.f16.f32 "
        "{%0,%1,%2,%3}, {%4,%5,%6,%7}, {%8,%9}, {%0,%1,%2,%3};"
        : "+f"(d[0]), "+f"(d[1]), "+f"(d[2]), "+f"(d[3])
        : "r"(a[0]), "r"(a[1]), "r"(a[2]), "r"(a[3]), "r"(b[0]), "r"(b[1]));
}
__device__ __forceinline__ float ex2f(float x) {
    float y; asm("ex2.approx.f32 %0, %1;" : "=f"(y) : "f"(x)); return y;
}
__device__ __forceinline__ uint32_t packbf(float a, float b) {
    __nv_bfloat162 t = __floats2bfloat162_rn(a, b);
    return *(uint32_t*)&t;
}
__device__ __forceinline__ uint32_t packhf(float a, float b) {
    __half2 t = __floats2half2_rn(a, b);
    return *(uint32_t*)&t;
}
#define CPA16(dst, src) \
    asm volatile("cp.async.cg.shared.global [%0], [%1], 16;" :: "r"(dst), "l"(src))

// ---------------------------------------------------------------------------
// split activations: fp32 [rows x 1024] -> bf16 [rows x 3072] [h|h|l]
// ---------------------------------------------------------------------------
__global__ void split_kernel(const float* __restrict__ in,
                             __nv_bfloat16* __restrict__ out, int rows)
{
    int i = blockIdx.x * blockDim.x + threadIdx.x;
    if (i >= rows * 256) return;
    int r  = i >> 8;
    int c4 = (i & 255) * 4;
    float4 v = *(const float4*)(in + (size_t)r * CDIM + c4);
    __nv_bfloat16 h[4], l[4];
    float vs[4] = {v.x, v.y, v.z, v.w};
#pragma unroll
    for (int t = 0; t < 4; t++) {
        h[t] = __float2bfloat16(vs[t]);
        l[t] = __float2bfloat16(vs[t] - __bfloat162float(h[t]));
    }
    __nv_bfloat16* o = out + (size_t)r * KSPLIT + c4;
    *(ushort4*)(o)            = *(ushort4*)h;
    *(ushort4*)(o + CDIM)     = *(ushort4*)h;
    *(ushort4*)(o + 2 * CDIM) = *(ushort4*)l;
}

// 4 weight splits in one launch: [h|l|h]. z<3 -> g_w3 block z, z==3 -> g_wo.
__global__ void splitw_kernel(const float* __restrict__ Wq, const float* __restrict__ Wk,
                              const float* __restrict__ Wv, const float* __restrict__ Wo)
{
    int z = blockIdx.y;
    const float* in = (z == 0) ? Wq : (z == 1) ? Wk : (z == 2) ? Wv : Wo;
    __nv_bfloat16* out = (z < 3) ? (g_w3 + (size_t)z * CDIM * KSPLIT) : g_wo;
    int i = blockIdx.x * blockDim.x + threadIdx.x;
    if (i >= CDIM * 256) return;
    int r  = i >> 8;
    int c4 = (i & 255) * 4;
    float4 v = *(const float4*)(in + (size_t)r * CDIM + c4);
    __nv_bfloat16 h[4], l[4];
    float vs[4] = {v.x, v.y, v.z, v.w};
#pragma unroll
    for (int t = 0; t < 4; t++) {
        h[t] = __float2bfloat16(vs[t]);
        l[t] = __float2bfloat16(vs[t] - __bfloat162float(h[t]));
    }
    __nv_bfloat16* o = out + (size_t)r * KSPLIT + c4;
    *(ushort4*)(o)            = *(ushort4*)h;
    *(ushort4*)(o + CDIM)     = *(ushort4*)l;
    *(ushort4*)(o + 2 * CDIM) = *(ushort4*)h;
}

// ---------------------------------------------------------------------------
// mma.sync bf16 NT GEMM: C = A'[M,3072] * B'[N,3072]^T, fp32 accum.
// CTA 128x128, 8 warps 2(m)x4(n) (64x32 warp tiles), 3-stage cp.async,
// 96KB smem -> 2 CTAs/SM.
// ---------------------------------------------------------------------------
#define GEMM_SMEM (3*32768)

__global__ __launch_bounds__(256, 2)
void gemm_mma_kernel(const __nv_bfloat16* __restrict__ A,
                     const __nv_bfloat16* __restrict__ B,
                     float* __restrict__ C, int M, int N)
{
    extern __shared__ char sm[];
    const uint32_t smb = smem_u32(sm);
    const int tid  = threadIdx.x;
    const int lane = tid & 31;
    const int wid  = tid >> 5;
    const int wm = wid & 1;
    const int wn = wid >> 1;
    const int bm = blockIdx.y * 128;
    const int bn = blockIdx.x * 128;

    const __nv_bfloat16* Ag = A + (size_t)bm * KSPLIT;
    const __nv_bfloat16* Bg = B + (size_t)bn * KSPLIT;

    auto prefetch = [&](int s) {
        const int buf = s % 3;
        const uint32_t ab = smb + buf * 32768;
        const uint32_t bb = ab + 16384;
        const __nv_bfloat16* a = Ag + s * 64;
        const __nv_bfloat16* b = Bg + s * 64;
#pragma unroll
        for (int i = 0; i < 4; i++) {
            int idx = tid + i * 256;
            int r = idx >> 3, ch = idx & 7;
            uint32_t o = r * 128 + ch * 16; o ^= (o >> 3) & 0x70;
            CPA16(ab + o, a + (size_t)r * KSPLIT + ch * 8);
            CPA16(bb + o, b + (size_t)r * KSPLIT + ch * 8);
        }
        asm volatile("cp.async.commit_group;");
    };

    float acc[4][4][4];
#pragma unroll
    for (int mt = 0; mt < 4; mt++)
#pragma unroll
        for (int nt = 0; nt < 4; nt++)
#pragma unroll
            for (int e = 0; e < 4; e++) acc[mt][nt][e] = 0.f;

    prefetch(0); prefetch(1); prefetch(2);

    for (int s = 0; s < NSTAGE; s++) {
        asm volatile("cp.async.wait_group 2;");
        __syncthreads();
        const int buf = s % 3;
        const uint32_t ab = smb + buf * 32768;
        const uint32_t bb = ab + 16384;
#pragma unroll
        for (int kk = 0; kk < 4; kk++) {
            uint32_t af[4][4];
            const int ar = wm * 64 + (lane & 15);
            const int ac = kk * 2 + (lane >> 4);
#pragma unroll
            for (int mt = 0; mt < 4; mt++) {
                uint32_t o = (ar + mt * 16) * 128 + ac * 16; o ^= (o >> 3) & 0x70;
                ldsm4(af[mt], ab + o);
            }
            uint32_t bfr[4][2];
            const int br = wn * 32 + ((lane >> 4) << 3) + (lane & 7);
            const int bc = kk * 2 + ((lane >> 3) & 1);
#pragma unroll
            for (int np = 0; np < 2; np++) {
                uint32_t o = (br + np * 16) * 128 + bc * 16; o ^= (o >> 3) & 0x70;
                uint32_t t4[4];
                ldsm4(t4, bb + o);
                bfr[np*2][0] = t4[0]; bfr[np*2][1] = t4[1];
                bfr[np*2+1][0] = t4[2]; bfr[np*2+1][1] = t4[3];
            }
#pragma unroll
            for (int mt = 0; mt < 4; mt++)
#pragma unroll
                for (int nt = 0; nt < 4; nt++)
                    mma16816(acc[mt][nt], af[mt], bfr[nt]);
        }
        __syncthreads();
        if (s + 3 < NSTAGE) prefetch(s + 3);
        else asm volatile("cp.async.commit_group;");
    }

    const int er = lane >> 2;
    const int ec = (lane & 3) * 2;
#pragma unroll
    for (int mt = 0; mt < 4; mt++) {
        int r0 = bm + wm * 64 + mt * 16 + er;
#pragma unroll
        for (int nt = 0; nt < 4; nt++) {
            int cc = bn + wn * 32 + nt * 8 + ec;
            *(float2*)(C + (size_t)r0 * N + cc) = make_float2(acc[mt][nt][0], acc[mt][nt][1]);
            *(float2*)(C + (size_t)(r0 + 8) * N + cc) = make_float2(acc[mt][nt][2], acc[mt][nt][3]);
        }
    }
}

// ---------------------------------------------------------------------------
// fused RoPE + split conversion. Reads fused qkv [rows x 3072].
// q/k -> bf16 h+l (q pre-scaled by 0.125*log2e), v -> fp16.  (R11 outputs)
// ---------------------------------------------------------------------------
#define QSCALE 0.180336878f   // 0.125 * log2(e)

__global__ void ropeconv_kernel(const float* __restrict__ qkv)
{
    int i = blockIdx.x * blockDim.x + threadIdx.x;
    if (i >= MROWS * CH * 4) return;
    const int c8   = (i & 3) * 8;
    const int rest = i >> 2;                 // (b*CT+t)*CH + h
    const int row  = rest >> 4;              // b*CT + t
    const int hh   = rest & 15;
    const int t    = row & (CT - 1);
    const size_t base  = (size_t)rest * CDH;             // output layout
    const size_t qbase = (size_t)row * 3072 + hh * CDH;  // fused input
    const size_t kbase = qbase + CDIM;
    const size_t vbase = qbase + 2 * CDIM;

    float q0[8], q1[8], k0[8], k1[8], v0[8], v1[8];
    *(float4*)(q0)   = *(const float4*)(qkv + qbase + c8);
    *(float4*)(q0+4) = *(const float4*)(qkv + qbase + c8 + 4);
    *(float4*)(q1)   = *(const float4*)(qkv + qbase + c8 + 32);
    *(float4*)(q1+4) = *(const float4*)(qkv + qbase + c8 + 36);
    *(float4*)(k0)   = *(const float4*)(qkv + kbase + c8);
    *(float4*)(k0+4) = *(const float4*)(qkv + kbase + c8 + 4);
    *(float4*)(k1)   = *(const float4*)(qkv + kbase + c8 + 32);
    *(float4*)(k1+4) = *(const float4*)(qkv + kbase + c8 + 36);
    *(float4*)(v0)   = *(const float4*)(qkv + vbase + c8);
    *(float4*)(v0+4) = *(const float4*)(qkv + vbase + c8 + 4);
    *(float4*)(v1)   = *(const float4*)(qkv + vbase + c8 + 32);
    *(float4*)(v1+4) = *(const float4*)(qkv + vbase + c8 + 36);

#pragma unroll
    for (int d = 0; d < 8; d++) {
        float invf = expf(-(float)(c8 + d) * (1.0f/32.0f) * logf(10000.0f));
        float ang = (float)t * invf, sv, cv;
        sincosf(ang, &sv, &cv);
        float a = q0[d], bq = q1[d];
        q0[d] = a * cv - bq * sv;  q1[d] = bq * cv + a * sv;
        float c = k0[d], dk = k1[d];
        k0[d] = c * cv - dk * sv;  k1[d] = dk * cv + c * sv;
    }

    uint32_t hw[4], lw[4];
    auto emit = [&](const float* src, float scale,
                    __nv_bfloat16* oh, __nv_bfloat16* ol) {
#pragma unroll
        for (int e = 0; e < 4; e++) {
            float a = src[2*e] * scale, b = src[2*e+1] * scale;
            float ah = __bfloat162float(__float2bfloat16_rn(a));
            float bh = __bfloat162float(__float2bfloat16_rn(b));
            hw[e] = packbf(a, b);
            lw[e] = packbf(a - ah, b - bh);
        }
        *(uint4*)oh = *(uint4*)hw;
        *(uint4*)ol = *(uint4*)lw;
    };
    auto emith = [&](const float* src, __half* oh) {
#pragma unroll
        for (int e = 0; e < 4; e++)
            hw[e] = packhf(src[2*e], src[2*e+1]);
        *(uint4*)oh = *(uint4*)hw;
    };
    emit(q0, QSCALE, g_qh + base + c8,      g_ql + base + c8);
    emit(q1, QSCALE, g_qh + base + c8 + 32, g_ql + base + c8 + 32);
    emit(k0, 1.0f,   g_kh + base + c8,      g_kl + base + c8);
    emit(k1, 1.0f,   g_kh + base + c8 + 32, g_kl + base + c8 + 32);
    emith(v0, g_vh + base + c8);
    emith(v1, g_vh + base + c8 + 32);
}

// ---------------------------------------------------------------------------
// Tensor-core causal flash attention (R11 version, unchanged).
// CTA = (b, h, 128 q-rows). 8 warps 2(M)x4(N). j-tiles of 128.
// S: 3-term bf16 split (d'=192). PV: single term, fp16 P x fp16 V.
// K/V double-buffered. Epilogue writes split [h|h|l] bf16 into g_a.
// ---------------------------------------------------------------------------
#define AQH 0
#define AQL 16384
#define AKV 32768          // + buf*49152 : KH +0, KL +16384, VH(fp16) +32768
#define APH 131072
#define ARED 165888
#define ATT_SMEM 169984
#define PROW 272           // P row stride bytes

__global__ __launch_bounds__(256, 1)
void attn_tc_kernel()
{
    extern __shared__ char sm[];
    const uint32_t smb = smem_u32(sm);
    float* red0 = (float*)(sm + ARED);
    float* red1 = (float*)(sm + ARED + 2048);

    const int tid  = threadIdx.x;
    const int lane = tid & 31;
    const int wid  = tid >> 5;
    const int wm = wid & 1, wn = wid >> 1;
    const int qt = gridDim.x - 1 - blockIdx.x;
    const int h  = blockIdx.y, b = blockIdx.z;
    const int q0 = qt * 128;

    // Q tiles
#pragma unroll
    for (int it = 0; it < 4; it++) {
        int idx = tid + it * 256;
        int r = idx >> 3, ch = idx & 7;
        uint32_t o = r * 128 + ch * 16; o ^= (o >> 3) & 0x70;
        size_t so = ((size_t)(b*CT + q0 + r)) * CDIM + h * CDH + ch * 8;
        CPA16(smb + AQH + o, g_qh + so);
        CPA16(smb + AQL + o, g_ql + so);
    }
    asm volatile("cp.async.commit_group;");

    auto pf_kv = [&](int jtn) {
        const uint32_t kvb = smb + AKV + (jtn & 1) * 49152;
        const int j0n = jtn * 128;
#pragma unroll
        for (int it = 0; it < 4; it++) {
            int idx = tid + it * 256;
            int r = idx >> 3, ch = idx & 7;
            uint32_t o = r * 128 + ch * 16; o ^= (o >> 3) & 0x70;
            size_t so = ((size_t)(b*CT + j0n + r)) * CDIM + h * CDH + ch * 8;
            CPA16(kvb + o,         g_kh + so);
            CPA16(kvb + 16384 + o, g_kl + so);
            CPA16(kvb + 32768 + o, g_vh + so);
        }
    };
    pf_kv(0);
    asm volatile("cp.async.commit_group;");

    float m_run[4][2], l_run[4][2];
    float oacc[4][2][4];
#pragma unroll
    for (int mt = 0; mt < 4; mt++)
#pragma unroll
        for (int p = 0; p < 2; p++) {
            m_run[mt][p] = -1e30f; l_run[mt][p] = 0.f;
            oacc[mt][p][0]=oacc[mt][p][1]=oacc[mt][p][2]=oacc[mt][p][3]=0.f;
        }

    const int rbase = (lane >> 2);
    const int cbase = (lane & 3) * 2;

    for (int jt = 0; jt <= qt; jt++) {
        __syncthreads();
        if (jt < qt) pf_kv(jt + 1);
        asm volatile("cp.async.commit_group;");
        asm volatile("cp.async.wait_group 1;");
        __syncthreads();

        const uint32_t kvb = smb + AKV + (jt & 1) * 49152;

        // ---- S = Q'.K'^T (12 k16 steps over d'=192) ----
        float sacc[4][4][4];
#pragma unroll
        for (int mt = 0; mt < 4; mt++)
#pragma unroll
            for (int nt = 0; nt < 4; nt++)
#pragma unroll
                for (int e = 0; e < 4; e++) sacc[mt][nt][e] = 0.f;

#pragma unroll
        for (int kk = 0; kk < 12; kk++) {
            const uint32_t qb = smb + (kk < 8 ? AQH : AQL);
            const uint32_t kb = kvb + (kk < 4 ? 0 : (kk < 8 ? 16384 : 0));
            const int kin = kk & 3;
            uint32_t af[4][4];
            const int ar = wm * 64 + (lane & 15);
            const int ac = kin * 2 + (lane >> 4);
#pragma unroll
            for (int mt = 0; mt < 4; mt++) {
                uint32_t o = (ar + mt * 16) * 128 + ac * 16; o ^= (o >> 3) & 0x70;
                ldsm4(af[mt], qb + o);
            }
            uint32_t bfr[4][2];
            const int br = wn * 32 + ((lane >> 4) << 3) + (lane & 7);
            const int bc = kin * 2 + ((lane >> 3) & 1);
#pragma unroll
            for (int np = 0; np < 2; np++) {
                uint32_t o = (br + np * 16) * 128 + bc * 16; o ^= (o >> 3) & 0x70;
                uint32_t t4[4];
                ldsm4(t4, kb + o);
                bfr[np*2][0] = t4[0]; bfr[np*2][1] = t4[1];
                bfr[np*2+1][0] = t4[2]; bfr[np*2+1][1] = t4[3];
            }
#pragma unroll
            for (int mt = 0; mt < 4; mt++)
#pragma unroll
                for (int nt = 0; nt < 4; nt++)
                    mma16816(sacc[mt][nt], af[mt], bfr[nt]);
        }

        if (jt == qt) {
#pragma unroll
            for (int mt = 0; mt < 4; mt++)
#pragma unroll
                for (int nt = 0; nt < 4; nt++)
#pragma unroll
                    for (int e = 0; e < 4; e++) {
                        int row = wm*64 + mt*16 + rbase + (e >> 1) * 8;
                        int col = wn*32 + nt*8 + cbase + (e & 1);
                        if (col > row) sacc[mt][nt][e] = -1e30f;
                    }
        }

        // ---- row max ----
        float mnew[4][2], alpha[4][2];
#pragma unroll
        for (int mt = 0; mt < 4; mt++)
#pragma unroll
            for (int p = 0; p < 2; p++) {
                float v = fmaxf(fmaxf(sacc[mt][0][2*p], sacc[mt][0][2*p+1]),
                                fmaxf(sacc[mt][1][2*p], sacc[mt][1][2*p+1]));
                v = fmaxf(v, fmaxf(fmaxf(sacc[mt][2][2*p], sacc[mt][2][2*p+1]),
                                   fmaxf(sacc[mt][3][2*p], sacc[mt][3][2*p+1])));
                v = fmaxf(v, __shfl_xor_sync(0xffffffffu, v, 1));
                v = fmaxf(v, __shfl_xor_sync(0xffffffffu, v, 2));
                if ((lane & 3) == 0)
                    red0[wn * 128 + wm*64 + mt*16 + rbase + p*8] = v;
            }
        __syncthreads();
#pragma unroll
        for (int mt = 0; mt < 4; mt++)
#pragma unroll
            for (int p = 0; p < 2; p++) {
                int row = wm*64 + mt*16 + rbase + p*8;
                float v = fmaxf(fmaxf(red0[row], red0[128 + row]),
                                fmaxf(red0[256 + row], red0[384 + row]));
                float mn = fmaxf(m_run[mt][p], v);
                alpha[mt][p] = ex2f(m_run[mt][p] - mn);
                mnew[mt][p] = mn;
                m_run[mt][p] = mn;
            }

        // ---- P = exp2(S - m) -> fp16 smem; row sums; rescale O ----
        float lsum[4][2] = {{0.f,0.f},{0.f,0.f},{0.f,0.f},{0.f,0.f}};
#pragma unroll
        for (int mt = 0; mt < 4; mt++) {
#pragma unroll
            for (int nt = 0; nt < 4; nt++) {
                int col = wn*32 + nt*8 + cbase;
#pragma unroll
                for (int p = 0; p < 2; p++) {
                    int row = wm*64 + mt*16 + rbase + p*8;
                    float p0 = ex2f(sacc[mt][nt][2*p]   - mnew[mt][p]);
                    float p1 = ex2f(sacc[mt][nt][2*p+1] - mnew[mt][p]);
                    lsum[mt][p] += p0 + p1;
                    *(uint32_t*)(sm + APH + row*PROW + col*2) = packhf(p0, p1);
                }
            }
        }
#pragma unroll
        for (int mt = 0; mt < 4; mt++)
#pragma unroll
            for (int p = 0; p < 2; p++) {
                float v = lsum[mt][p];
                v += __shfl_xor_sync(0xffffffffu, v, 1);
                v += __shfl_xor_sync(0xffffffffu, v, 2);
                if ((lane & 3) == 0)
                    red1[wn * 128 + wm*64 + mt*16 + rbase + p*8] = v;
                oacc[mt][0][2*p]   *= alpha[mt][p];
                oacc[mt][0][2*p+1] *= alpha[mt][p];
                oacc[mt][1][2*p]   *= alpha[mt][p];
                oacc[mt][1][2*p+1] *= alpha[mt][p];
            }
        __syncthreads();
#pragma unroll
        for (int mt = 0; mt < 4; mt++)
#pragma unroll
            for (int p = 0; p < 2; p++) {
                int row = wm*64 + mt*16 + rbase + p*8;
                float v = red1[row] + red1[128 + row] + red1[256 + row] + red1[384 + row];
                l_run[mt][p] = l_run[mt][p] * alpha[mt][p] + v;
            }

        // ---- PV: single term, fp16 P x fp16 V ----
        const uint32_t vb = kvb + 32768;
#pragma unroll
        for (int kk = 0; kk < 8; kk++) {
            uint32_t af[4][4];
            const int ar = wm * 64 + (lane & 15);
            const int ac = kk * 2 + (lane >> 4);
#pragma unroll
            for (int mt = 0; mt < 4; mt++)
                ldsm4(af[mt], smb + APH + (ar + mt*16)*PROW + ac*16);
            uint32_t bv[2][2];
            const int vr = kk * 16 + (lane & 15);
#pragma unroll
            for (int np = 0; np < 2; np++) {
                uint32_t o = vr * 128 + (wn*16 + np*8) * 2; o ^= (o >> 3) & 0x70;
                ldsm2t(bv[np], vb + o);
            }
#pragma unroll
            for (int mt = 0; mt < 4; mt++)
#pragma unroll
                for (int np = 0; np < 2; np++)
                    mma16816h(oacc[mt][np], af[mt], bv[np]);
        }
    }

    // ---- epilogue: write split activations [h|h|l] straight into g_a ----
#pragma unroll
    for (int mt = 0; mt < 4; mt++)
#pragma unroll
        for (int p = 0; p < 2; p++) {
            float inv = 1.0f / l_run[mt][p];
            size_t rg = (size_t)(b*CT) + q0 + wm*64 + mt*16 + rbase + p*8;
#pragma unroll
            for (int np = 0; np < 2; np++) {
                int col = h * CDH + wn*16 + np*8 + cbase;
                float v0 = oacc[mt][np][2*p] * inv;
                float v1 = oacc[mt][np][2*p+1] * inv;
                float h0 = __bfloat162float(__float2bfloat16_rn(v0));
                float h1 = __bfloat162float(__float2bfloat16_rn(v1));
                uint32_t hwv = packbf(v0, v1);
                uint32_t lwv = packbf(v0 - h0, v1 - h1);
                __nv_bfloat16* oa = g_a + rg * KSPLIT + col;
                *(uint32_t*)(oa)            = hwv;
                *(uint32_t*)(oa + CDIM)     = hwv;
                *(uint32_t*)(oa + 2*CDIM)   = lwv;
            }
        }
}

// ---------------------------------------------------------------------------
extern "C" void kernel_launch(void* const* d_in, const int* in_sizes, int n_in,
                              void* d_out, int out_size)
{
    const float* x  = (const float*)d_in[0];
    const float* Wq = (const float*)d_in[1];
    const float* Wk = (const float*)d_in[2];
    const float* Wv = (const float*)d_in[3];
    const float* Wo = (const float*)d_in[4];
    float* out = (float*)d_out;

    float *qkvp;
    __nv_bfloat16 *a2, *w3, *wo2;
    cudaGetSymbolAddress((void**)&qkvp, g_qkv);
    cudaGetSymbolAddress((void**)&a2,  g_a);
    cudaGetSymbolAddress((void**)&w3,  g_w3);
    cudaGetSymbolAddress((void**)&wo2, g_wo);

    cudaFuncSetAttribute(gemm_mma_kernel,
                         cudaFuncAttributeMaxDynamicSharedMemorySize, GEMM_SMEM);
    cudaFuncSetAttribute(attn_tc_kernel,
                         cudaFuncAttributeMaxDynamicSharedMemorySize, ATT_SMEM);

    int na = MROWS * 256;
    split_kernel<<<(na + 255)/256, 256>>>(x, a2, MROWS);
    splitw_kernel<<<dim3(CDIM, 4), 256>>>(Wq, Wk, Wv, Wo);

    // fused QKV projection: C[4096, 3072], grid 24x32 = 768 CTAs
    gemm_mma_kernel<<<dim3(3*CDIM/128, MROWS/128), 256, GEMM_SMEM>>>(
        a2, w3, qkvp, MROWS, 3*CDIM);

    ropeconv_kernel<<<(MROWS*CH*4 + 255)/256, 256>>>(qkvp);

    attn_tc_kernel<<<dim3(CT/128, CH, CB), 256, ATT_SMEM>>>();

    gemm_mma_kernel<<<dim3(CDIM/128, MROWS/128), 256, GEMM_SMEM>>>(
        a2, wo2, out, MROWS, CDIM);
}